// round 13
// baseline (speedup 1.0000x reference)
#include <cuda_runtime.h>
#include <math.h>
#include <stdint.h>

// ---------------------------------------------------------------------------
// ElectricOverflow. Grid 512x512x8 (8MB, L2-resident), padded both sides.
//
// Locked-in findings (R2-R12):
//  * Scatter pinned ~17us real across 6 variants -> LTS/LSU wall. Keep R4
//    emission exactly (z-border cull, sector-local pairing).
//  * PDL across both boundaries: -2.0us (R12, matched prediction).
//  * Structure [zero, scatter, reduce]; reduce-with-reset loses (R5, R9).
// This round: flatten k_zero (2048 blocks x 1 float4/thread, no in-thread
// store chain) to shorten the wall at the head of the critical path; finer
// reduce blocks for ramp straggle.
// ---------------------------------------------------------------------------

#define NM_ 250000
#define NT_ 8000
#define NF_ 60000
#define N_  (NM_ + NT_ + NF_)    // 318000
#define NX_ 512
#define NY_ 512
#define NZ_ 8
#define NBINS_ (NX_ * NY_ * NZ_) // 2097152
#define PADF_ 4424               // covers ix/iy in [-1,512], z in [1,6]

#define SQRT2H 0.7071067811865476f
#define C1 0.41421356237309515f  // sqrt2 - 1
#define C2 0.5857864376269049f   // 2 - sqrt2

__device__ __align__(128) float g_pad[PADF_ + NBINS_ + PADF_];
#define GRID_B (g_pad + PADF_)

__device__ __forceinline__ void red1(float* p, float v) {
    asm volatile("red.global.add.f32 [%0], %1;" :: "l"(p), "f"(v) : "memory");
}
__device__ __forceinline__ void red2(float* p, float a, float b) {
    asm volatile("red.global.add.v2.f32 [%0], {%1, %2};"
                 :: "l"(p), "f"(a), "f"(b) : "memory");
}

// ---------------------------------------------------------------------------
// Zero: 2048 blocks x 256 thr x 1 float4 — maximal block parallelism,
// no in-thread store serialization -> minimal wall before PDL release.
// ---------------------------------------------------------------------------
__global__ void k_zero(float* __restrict__ out) {
    int i = blockIdx.x * blockDim.x + threadIdx.x;  // 524288 threads
    reinterpret_cast<float4*>(GRID_B)[i] = make_float4(0.f, 0.f, 0.f, 0.f);
    if (i == 0) { out[0] = 0.0f; out[1] = 1.0f; }   // border density = 1.0
    cudaTriggerProgrammaticLaunchCompletion();
}

// Emit up to 3 z-lane REDs, pairing adjacent surviving lanes when 8B-aligned.
// Never crosses the 32B z-row sector.
__device__ __forceinline__ void emit_z(float* p, float wxy,
                                       float v0, float v1, float v2,
                                       bool e0, bool e1, bool e2, bool even0) {
    if (e0 && e1 && even0) {
        red2(p, wxy * v0, wxy * v1);
        if (e2) red1(p + 2, wxy * v2);
    } else {
        if (e0) red1(p, wxy * v0);
        if (e1 && e2 && !even0) red2(p + 1, wxy * v1, wxy * v2);
        else {
            if (e1) red1(p + 1, wxy * v1);
            if (e2) red1(p + 2, wxy * v2);
        }
    }
}

// ---------------------------------------------------------------------------
// Fused scatter (1 node/thread, 256-thr blocks — champion config).
// PDL: input loads + window math run BEFORE cudaGridDependencySynchronize();
// only the REDs wait for the zeroed grid.
// ---------------------------------------------------------------------------
__global__ void k_scatter(const float* __restrict__ pos,
                          const float* __restrict__ nsx,
                          const float* __restrict__ nsy,
                          const float* __restrict__ nsz) {
    int t = blockIdx.x * blockDim.x + threadIdx.x;
    if (t >= N_) {
        cudaGridDependencySynchronize();
        return;
    }

    bool isFill = (t >= NM_ + NF_);
    int j = isFill ? (t - NF_) : ((t < NM_) ? t : (t + NT_));

    float sx = nsx[j], sy = nsy[j], sz = nsz[j];
    float px = pos[j], py = pos[N_ + j], pz = pos[2 * N_ + j];

    if (!isFill) {
        const float w = sx * sy * sz * 0.35355339059327373f;  // /(2*sqrt2)
        float x0 = px + 0.5f * sx - SQRT2H;
        float y0 = py + 0.5f * sy - SQRT2H;
        float z0 = pz + 0.5f * sz - SQRT2H;

        float fxf = floorf(x0), fyf = floorf(y0), fzf = floorf(z0);
        int ix0 = (int)fxf, iy0 = (int)fyf, iz0 = (int)fzf;
        float fx = x0 - fxf, fy = y0 - fyf, fz = z0 - fzf;

        float ox[3] = { 1.0f - fx, fminf(fx + C1, 1.0f), fmaxf(fx - C2, 0.0f) };
        float oy[3] = { 1.0f - fy, fminf(fy + C1, 1.0f), fmaxf(fy - C2, 0.0f) };

        float v0 = 1.0f - fz;
        float v1 = fminf(fz + C1, 1.0f);
        float v2 = fmaxf(fz - C2, 0.0f);
        bool e0 = (iz0 >= 1) & (iz0 <= 6);
        bool e1 = (iz0 >= 0) & (iz0 <= 5);
        bool e2 = (iz0 >= -1) & (iz0 <= 4) & (v2 > 0.0f);
        bool even0 = ((iz0 & 1) == 0);

        cudaGridDependencySynchronize();       // wait for zeroed grid
        if (!(e0 | e1 | e2)) return;

#pragma unroll
        for (int a = 0; a < 3; ++a) {
            if (ox[a] == 0.0f) continue;          // only a==2 can be 0
            float wx = w * ox[a];
#pragma unroll
            for (int b = 0; b < 3; ++b) {
                if (oy[b] == 0.0f) continue;
                float* p = GRID_B + (((ix0 + a) * NY_ + (iy0 + b)) << 3) + iz0;
                emit_z(p, wx * oy[b], v0, v1, v2, e0, e1, e2, even0);
            }
        }
    } else {
        float fxf = floorf(px), fyf = floorf(py), fzf = floorf(pz);
        int ix0 = (int)fxf, iy0 = (int)fyf, iz0 = (int)fzf;  // iz0 in [0,6]
        float fx = px - fxf, fy = py - fyf, fz = pz - fzf;

        float ox[2] = { fminf(1.0f - fx, sx), fmaxf(fx + sx - 1.0f, 0.0f) };
        float oy[2] = { fminf(1.0f - fy, sy), fmaxf(fy + sy - 1.0f, 0.0f) };
        float v0 = fminf(1.0f - fz, sz);
        float v1 = fmaxf(fz + sz - 1.0f, 0.0f);
        bool e0 = (iz0 >= 1);
        bool e1 = (iz0 <= 5) & (v1 > 0.0f);
        bool even0 = ((iz0 & 1) == 0);

        cudaGridDependencySynchronize();       // wait for zeroed grid
        if (!(e0 | e1)) return;

#pragma unroll
        for (int a = 0; a < 2; ++a) {
            if (ox[a] == 0.0f) continue;
#pragma unroll
            for (int b = 0; b < 2; ++b) {
                if (oy[b] == 0.0f) continue;
                float wxy = ox[a] * oy[b];
                float* p = GRID_B + (((ix0 + a) * NY_ + (iy0 + b)) << 3) + iz0;
                if (e0 && e1 && even0) red2(p, wxy * v0, wxy * v1);
                else {
                    if (e0) red1(p, wxy * v0);
                    if (e1) red1(p + 1, wxy * v1);
                }
            }
        }
    }
    cudaTriggerProgrammaticLaunchCompletion();
}

// ---------------------------------------------------------------------------
// Reduction (load-only): one thread per (x,y) z-row, 2x float4, interior
// z=1..6. 128-thr blocks for finer post-sync ramp. PDL: index math
// pre-sync; grid loads post-sync.
// ---------------------------------------------------------------------------
__global__ void k_reduce(float* __restrict__ out) {
    int t = blockIdx.x * blockDim.x + threadIdx.x;  // 512*512 threads
    float s = 0.0f, m = 0.0f;
    int ix = t >> 9;
    int iy = t & 511;
    bool interior = (ix >= 1) & (ix <= NX_ - 2) & (iy >= 1) & (iy <= NY_ - 2);

    cudaGridDependencySynchronize();           // wait for scatter's REDs

    if (interior) {
        const float4* g4 = reinterpret_cast<const float4*>(GRID_B) + t * 2;
        float4 a = g4[0];
        float4 b = g4[1];
        s = fmaxf(a.y - 1.0f, 0.0f) + fmaxf(a.z - 1.0f, 0.0f) +
            fmaxf(a.w - 1.0f, 0.0f) + fmaxf(b.x - 1.0f, 0.0f) +
            fmaxf(b.y - 1.0f, 0.0f) + fmaxf(b.z - 1.0f, 0.0f);
        m = fmaxf(fmaxf(fmaxf(a.y, a.z), fmaxf(a.w, b.x)), fmaxf(b.y, b.z));
    }
#pragma unroll
    for (int o = 16; o > 0; o >>= 1) {
        s += __shfl_down_sync(0xffffffffu, s, o);
        m = fmaxf(m, __shfl_down_sync(0xffffffffu, m, o));
    }
    __shared__ float ss[4], sm[4];
    int lane = threadIdx.x & 31;
    int wid = threadIdx.x >> 5;
    if (lane == 0) { ss[wid] = s; sm[wid] = m; }
    __syncthreads();
    if (wid == 0) {
        int nw = blockDim.x >> 5;
        s = (lane < nw) ? ss[lane] : 0.0f;
        m = (lane < nw) ? sm[lane] : 0.0f;
#pragma unroll
        for (int o = 2; o > 0; o >>= 1) {
            s += __shfl_down_sync(0xffffffffu, s, o);
            m = fmaxf(m, __shfl_down_sync(0xffffffffu, m, o));
        }
        if (lane == 0) {
            atomicAdd(&out[0], s);
            atomicMax(reinterpret_cast<int*>(&out[1]), __float_as_int(m));
        }
    }
}

extern "C" void kernel_launch(void* const* d_in, const int* in_sizes, int n_in,
                              void* d_out, int out_size) {
    const float* pos = (const float*)d_in[0];
    const float* nsx = (const float*)d_in[1];
    const float* nsy = (const float*)d_in[2];
    const float* nsz = (const float*)d_in[3];
    float* out = (float*)d_out;

    // 1) zero (plain launch)
    k_zero<<<2048, 256>>>(out);

    // 2) scatter — PDL-dependent on zero
    {
        cudaLaunchConfig_t cfg = {};
        cfg.gridDim = dim3((N_ + 255) / 256);
        cfg.blockDim = dim3(256);
        cudaLaunchAttribute attr[1];
        attr[0].id = cudaLaunchAttributeProgrammaticStreamSerialization;
        attr[0].val.programmaticStreamSerializationAllowed = 1;
        cfg.attrs = attr;
        cfg.numAttrs = 1;
        cudaLaunchKernelEx(&cfg, k_scatter, pos, nsx, nsy, nsz);
    }

    // 3) reduce — PDL-dependent on scatter
    {
        cudaLaunchConfig_t cfg = {};
        cfg.gridDim = dim3((NX_ * NY_) / 128);
        cfg.blockDim = dim3(128);
        cudaLaunchAttribute attr[1];
        attr[0].id = cudaLaunchAttributeProgrammaticStreamSerialization;
        attr[0].val.programmaticStreamSerializationAllowed = 1;
        cfg.attrs = attr;
        cfg.numAttrs = 1;
        cudaLaunchKernelEx(&cfg, k_reduce, out);
    }
}

// round 14
// speedup vs baseline: 1.0822x; 1.0822x over previous
#include <cuda_runtime.h>
#include <math.h>
#include <stdint.h>

// ---------------------------------------------------------------------------
// ElectricOverflow. Grid 512x512x8 (8MB, L2-resident), padded both sides.
//
// Locked-in findings (R2-R13):
//  * Scatter pinned ~17us real across 6 variants -> LTS/LSU wall. R4
//    emission kept exactly (z-border cull, sector-local pairing).
//  * PDL across both boundaries: -2.0us (R12 champion, 25.06us).
//  * Tiny-kernel wall = f(block count, balance): 2048x1 zero regressed
//    (ramp-dominated); 512x4 good. This round tests the 1024x2 midpoint.
// ---------------------------------------------------------------------------

#define NM_ 250000
#define NT_ 8000
#define NF_ 60000
#define N_  (NM_ + NT_ + NF_)    // 318000
#define NX_ 512
#define NY_ 512
#define NZ_ 8
#define NBINS_ (NX_ * NY_ * NZ_) // 2097152
#define PADF_ 4424               // covers ix/iy in [-1,512], z in [1,6]

#define SQRT2H 0.7071067811865476f
#define C1 0.41421356237309515f  // sqrt2 - 1
#define C2 0.5857864376269049f   // 2 - sqrt2

__device__ __align__(128) float g_pad[PADF_ + NBINS_ + PADF_];
#define GRID_B (g_pad + PADF_)

__device__ __forceinline__ void red1(float* p, float v) {
    asm volatile("red.global.add.f32 [%0], %1;" :: "l"(p), "f"(v) : "memory");
}
__device__ __forceinline__ void red2(float* p, float a, float b) {
    asm volatile("red.global.add.v2.f32 [%0], {%1, %2};"
                 :: "l"(p), "f"(a), "f"(b) : "memory");
}

// ---------------------------------------------------------------------------
// Zero: 1024 blocks x 256 thr x 2 float4 (midpoint of 512x4 / 2048x1).
// ---------------------------------------------------------------------------
__global__ void k_zero(float* __restrict__ out) {
    int i = blockIdx.x * blockDim.x + threadIdx.x;  // 262144 threads
    float4* g4 = reinterpret_cast<float4*>(GRID_B);
    const float4 z = make_float4(0.f, 0.f, 0.f, 0.f);
    g4[i] = z;
    g4[i + 262144] = z;
    if (i == 0) { out[0] = 0.0f; out[1] = 1.0f; }   // border density = 1.0
    cudaTriggerProgrammaticLaunchCompletion();
}

// Emit up to 3 z-lane REDs, pairing adjacent surviving lanes when 8B-aligned.
// Never crosses the 32B z-row sector.
__device__ __forceinline__ void emit_z(float* p, float wxy,
                                       float v0, float v1, float v2,
                                       bool e0, bool e1, bool e2, bool even0) {
    if (e0 && e1 && even0) {
        red2(p, wxy * v0, wxy * v1);
        if (e2) red1(p + 2, wxy * v2);
    } else {
        if (e0) red1(p, wxy * v0);
        if (e1 && e2 && !even0) red2(p + 1, wxy * v1, wxy * v2);
        else {
            if (e1) red1(p + 1, wxy * v1);
            if (e2) red1(p + 2, wxy * v2);
        }
    }
}

// ---------------------------------------------------------------------------
// Fused scatter (1 node/thread, 256-thr blocks — champion config).
// PDL: input loads + window math run BEFORE cudaGridDependencySynchronize();
// only the REDs wait for the zeroed grid.
// ---------------------------------------------------------------------------
__global__ void k_scatter(const float* __restrict__ pos,
                          const float* __restrict__ nsx,
                          const float* __restrict__ nsy,
                          const float* __restrict__ nsz) {
    int t = blockIdx.x * blockDim.x + threadIdx.x;
    if (t >= N_) {
        cudaGridDependencySynchronize();
        return;
    }

    bool isFill = (t >= NM_ + NF_);
    int j = isFill ? (t - NF_) : ((t < NM_) ? t : (t + NT_));

    float sx = nsx[j], sy = nsy[j], sz = nsz[j];
    float px = pos[j], py = pos[N_ + j], pz = pos[2 * N_ + j];

    if (!isFill) {
        const float w = sx * sy * sz * 0.35355339059327373f;  // /(2*sqrt2)
        float x0 = px + 0.5f * sx - SQRT2H;
        float y0 = py + 0.5f * sy - SQRT2H;
        float z0 = pz + 0.5f * sz - SQRT2H;

        float fxf = floorf(x0), fyf = floorf(y0), fzf = floorf(z0);
        int ix0 = (int)fxf, iy0 = (int)fyf, iz0 = (int)fzf;
        float fx = x0 - fxf, fy = y0 - fyf, fz = z0 - fzf;

        float ox[3] = { 1.0f - fx, fminf(fx + C1, 1.0f), fmaxf(fx - C2, 0.0f) };
        float oy[3] = { 1.0f - fy, fminf(fy + C1, 1.0f), fmaxf(fy - C2, 0.0f) };

        float v0 = 1.0f - fz;
        float v1 = fminf(fz + C1, 1.0f);
        float v2 = fmaxf(fz - C2, 0.0f);
        bool e0 = (iz0 >= 1) & (iz0 <= 6);
        bool e1 = (iz0 >= 0) & (iz0 <= 5);
        bool e2 = (iz0 >= -1) & (iz0 <= 4) & (v2 > 0.0f);
        bool even0 = ((iz0 & 1) == 0);

        cudaGridDependencySynchronize();       // wait for zeroed grid
        if (!(e0 | e1 | e2)) return;

#pragma unroll
        for (int a = 0; a < 3; ++a) {
            if (ox[a] == 0.0f) continue;          // only a==2 can be 0
            float wx = w * ox[a];
#pragma unroll
            for (int b = 0; b < 3; ++b) {
                if (oy[b] == 0.0f) continue;
                float* p = GRID_B + (((ix0 + a) * NY_ + (iy0 + b)) << 3) + iz0;
                emit_z(p, wx * oy[b], v0, v1, v2, e0, e1, e2, even0);
            }
        }
    } else {
        float fxf = floorf(px), fyf = floorf(py), fzf = floorf(pz);
        int ix0 = (int)fxf, iy0 = (int)fyf, iz0 = (int)fzf;  // iz0 in [0,6]
        float fx = px - fxf, fy = py - fyf, fz = pz - fzf;

        float ox[2] = { fminf(1.0f - fx, sx), fmaxf(fx + sx - 1.0f, 0.0f) };
        float oy[2] = { fminf(1.0f - fy, sy), fmaxf(fy + sy - 1.0f, 0.0f) };
        float v0 = fminf(1.0f - fz, sz);
        float v1 = fmaxf(fz + sz - 1.0f, 0.0f);
        bool e0 = (iz0 >= 1);
        bool e1 = (iz0 <= 5) & (v1 > 0.0f);
        bool even0 = ((iz0 & 1) == 0);

        cudaGridDependencySynchronize();       // wait for zeroed grid
        if (!(e0 | e1)) return;

#pragma unroll
        for (int a = 0; a < 2; ++a) {
            if (ox[a] == 0.0f) continue;
#pragma unroll
            for (int b = 0; b < 2; ++b) {
                if (oy[b] == 0.0f) continue;
                float wxy = ox[a] * oy[b];
                float* p = GRID_B + (((ix0 + a) * NY_ + (iy0 + b)) << 3) + iz0;
                if (e0 && e1 && even0) red2(p, wxy * v0, wxy * v1);
                else {
                    if (e0) red1(p, wxy * v0);
                    if (e1) red1(p + 1, wxy * v1);
                }
            }
        }
    }
    cudaTriggerProgrammaticLaunchCompletion();
}

// ---------------------------------------------------------------------------
// Reduction (load-only, champion config): one thread per (x,y) z-row,
// 2x float4, interior z=1..6. PDL: index math pre-sync; loads post-sync.
// ---------------------------------------------------------------------------
__global__ void k_reduce(float* __restrict__ out) {
    int t = blockIdx.x * blockDim.x + threadIdx.x;  // 512*512 threads
    float s = 0.0f, m = 0.0f;
    int ix = t >> 9;
    int iy = t & 511;
    bool interior = (ix >= 1) & (ix <= NX_ - 2) & (iy >= 1) & (iy <= NY_ - 2);

    cudaGridDependencySynchronize();           // wait for scatter's REDs

    if (interior) {
        const float4* g4 = reinterpret_cast<const float4*>(GRID_B) + t * 2;
        float4 a = g4[0];
        float4 b = g4[1];
        s = fmaxf(a.y - 1.0f, 0.0f) + fmaxf(a.z - 1.0f, 0.0f) +
            fmaxf(a.w - 1.0f, 0.0f) + fmaxf(b.x - 1.0f, 0.0f) +
            fmaxf(b.y - 1.0f, 0.0f) + fmaxf(b.z - 1.0f, 0.0f);
        m = fmaxf(fmaxf(fmaxf(a.y, a.z), fmaxf(a.w, b.x)), fmaxf(b.y, b.z));
    }
#pragma unroll
    for (int o = 16; o > 0; o >>= 1) {
        s += __shfl_down_sync(0xffffffffu, s, o);
        m = fmaxf(m, __shfl_down_sync(0xffffffffu, m, o));
    }
    __shared__ float ss[8], sm[8];
    int lane = threadIdx.x & 31;
    int wid = threadIdx.x >> 5;
    if (lane == 0) { ss[wid] = s; sm[wid] = m; }
    __syncthreads();
    if (wid == 0) {
        int nw = blockDim.x >> 5;
        s = (lane < nw) ? ss[lane] : 0.0f;
        m = (lane < nw) ? sm[lane] : 0.0f;
#pragma unroll
        for (int o = 4; o > 0; o >>= 1) {
            s += __shfl_down_sync(0xffffffffu, s, o);
            m = fmaxf(m, __shfl_down_sync(0xffffffffu, m, o));
        }
        if (lane == 0) {
            atomicAdd(&out[0], s);
            atomicMax(reinterpret_cast<int*>(&out[1]), __float_as_int(m));
        }
    }
}

extern "C" void kernel_launch(void* const* d_in, const int* in_sizes, int n_in,
                              void* d_out, int out_size) {
    const float* pos = (const float*)d_in[0];
    const float* nsx = (const float*)d_in[1];
    const float* nsy = (const float*)d_in[2];
    const float* nsz = (const float*)d_in[3];
    float* out = (float*)d_out;

    // 1) zero (plain launch)
    k_zero<<<1024, 256>>>(out);

    // 2) scatter — PDL-dependent on zero
    {
        cudaLaunchConfig_t cfg = {};
        cfg.gridDim = dim3((N_ + 255) / 256);
        cfg.blockDim = dim3(256);
        cudaLaunchAttribute attr[1];
        attr[0].id = cudaLaunchAttributeProgrammaticStreamSerialization;
        attr[0].val.programmaticStreamSerializationAllowed = 1;
        cfg.attrs = attr;
        cfg.numAttrs = 1;
        cudaLaunchKernelEx(&cfg, k_scatter, pos, nsx, nsy, nsz);
    }

    // 3) reduce — PDL-dependent on scatter
    {
        cudaLaunchConfig_t cfg = {};
        cfg.gridDim = dim3((NX_ * NY_) / 256);
        cfg.blockDim = dim3(256);
        cudaLaunchAttribute attr[1];
        attr[0].id = cudaLaunchAttributeProgrammaticStreamSerialization;
        attr[0].val.programmaticStreamSerializationAllowed = 1;
        cfg.attrs = attr;
        cfg.numAttrs = 1;
        cudaLaunchKernelEx(&cfg, k_reduce, out);
    }
}

// round 15
// speedup vs baseline: 1.0918x; 1.0089x over previous
#include <cuda_runtime.h>
#include <math.h>
#include <stdint.h>

// ---------------------------------------------------------------------------
// ElectricOverflow. Grid 512x512x8 (8MB, L2-resident), padded both sides.
//
// Locked-in findings (R2-R14):
//  * Scatter ~17us: bound by LTS atomic throughput at 60% util; sector
//    count/lanes/instructions all non-binding.
//  * PDL on both boundaries: -2us. Zero shape 512x4 optimal (scan done).
// This round: y-outer/x-inner emission. x-slabs are 16KB apart (different
// L2 hash slices); y-rows are 32B apart (SAME slice, bit7-transparent
// 128B granularity). Old order fired same-slice bursts; new order
// interleaves slices per thread -> smoother LTS arrivals.
// ---------------------------------------------------------------------------

#define NM_ 250000
#define NT_ 8000
#define NF_ 60000
#define N_  (NM_ + NT_ + NF_)    // 318000
#define NX_ 512
#define NY_ 512
#define NZ_ 8
#define NBINS_ (NX_ * NY_ * NZ_) // 2097152
#define PADF_ 4424               // covers ix/iy in [-1,512], z in [1,6]

#define SQRT2H 0.7071067811865476f
#define C1 0.41421356237309515f  // sqrt2 - 1
#define C2 0.5857864376269049f   // 2 - sqrt2

__device__ __align__(128) float g_pad[PADF_ + NBINS_ + PADF_];
#define GRID_B (g_pad + PADF_)

__device__ __forceinline__ void red1(float* p, float v) {
    asm volatile("red.global.add.f32 [%0], %1;" :: "l"(p), "f"(v) : "memory");
}
__device__ __forceinline__ void red2(float* p, float a, float b) {
    asm volatile("red.global.add.v2.f32 [%0], {%1, %2};"
                 :: "l"(p), "f"(a), "f"(b) : "memory");
}

// ---------------------------------------------------------------------------
// Zero (proven optimal shape): 512 blocks x 256 thr x 4 float4.
// ---------------------------------------------------------------------------
__global__ void k_zero(float* __restrict__ out) {
    int i = blockIdx.x * blockDim.x + threadIdx.x;  // 131072 threads
    float4* g4 = reinterpret_cast<float4*>(GRID_B);
    const float4 z = make_float4(0.f, 0.f, 0.f, 0.f);
#pragma unroll
    for (int k = 0; k < 4; ++k) g4[i + k * 131072] = z;
    if (i == 0) { out[0] = 0.0f; out[1] = 1.0f; }   // border density = 1.0
    cudaTriggerProgrammaticLaunchCompletion();
}

// Emit up to 3 z-lane REDs, pairing adjacent surviving lanes when 8B-aligned.
// Never crosses the 32B z-row sector.
__device__ __forceinline__ void emit_z(float* p, float wxy,
                                       float v0, float v1, float v2,
                                       bool e0, bool e1, bool e2, bool even0) {
    if (e0 && e1 && even0) {
        red2(p, wxy * v0, wxy * v1);
        if (e2) red1(p + 2, wxy * v2);
    } else {
        if (e0) red1(p, wxy * v0);
        if (e1 && e2 && !even0) red2(p + 1, wxy * v1, wxy * v2);
        else {
            if (e1) red1(p + 1, wxy * v1);
            if (e2) red1(p + 2, wxy * v2);
        }
    }
}

// ---------------------------------------------------------------------------
// Fused scatter (1 node/thread, 256-thr blocks). PDL: loads + window math
// pre-sync; REDs post-sync. Emission is y-OUTER / x-INNER so consecutive
// REDs land in different L2 slices (x-slabs 16KB apart).
// ---------------------------------------------------------------------------
__global__ void k_scatter(const float* __restrict__ pos,
                          const float* __restrict__ nsx,
                          const float* __restrict__ nsy,
                          const float* __restrict__ nsz) {
    int t = blockIdx.x * blockDim.x + threadIdx.x;
    if (t >= N_) {
        cudaGridDependencySynchronize();
        return;
    }

    bool isFill = (t >= NM_ + NF_);
    int j = isFill ? (t - NF_) : ((t < NM_) ? t : (t + NT_));

    float sx = nsx[j], sy = nsy[j], sz = nsz[j];
    float px = pos[j], py = pos[N_ + j], pz = pos[2 * N_ + j];

    if (!isFill) {
        const float w = sx * sy * sz * 0.35355339059327373f;  // /(2*sqrt2)
        float x0 = px + 0.5f * sx - SQRT2H;
        float y0 = py + 0.5f * sy - SQRT2H;
        float z0 = pz + 0.5f * sz - SQRT2H;

        float fxf = floorf(x0), fyf = floorf(y0), fzf = floorf(z0);
        int ix0 = (int)fxf, iy0 = (int)fyf, iz0 = (int)fzf;
        float fx = x0 - fxf, fy = y0 - fyf, fz = z0 - fzf;

        float ox[3] = { 1.0f - fx, fminf(fx + C1, 1.0f), fmaxf(fx - C2, 0.0f) };
        float oy[3] = { 1.0f - fy, fminf(fy + C1, 1.0f), fmaxf(fy - C2, 0.0f) };

        float v0 = 1.0f - fz;
        float v1 = fminf(fz + C1, 1.0f);
        float v2 = fmaxf(fz - C2, 0.0f);
        bool e0 = (iz0 >= 1) & (iz0 <= 6);
        bool e1 = (iz0 >= 0) & (iz0 <= 5);
        bool e2 = (iz0 >= -1) & (iz0 <= 4) & (v2 > 0.0f);
        bool even0 = ((iz0 & 1) == 0);

        cudaGridDependencySynchronize();       // wait for zeroed grid
        if (!(e0 | e1 | e2)) return;

        // y-outer / x-inner: consecutive REDs hit different x-slabs
        // (16KB apart -> different L2 hash slices).
#pragma unroll
        for (int b = 0; b < 3; ++b) {
            if (oy[b] == 0.0f) continue;          // only b==2 can be 0
            float wy = w * oy[b];
#pragma unroll
            for (int a = 0; a < 3; ++a) {
                if (ox[a] == 0.0f) continue;
                float* p = GRID_B + (((ix0 + a) * NY_ + (iy0 + b)) << 3) + iz0;
                emit_z(p, wy * ox[a], v0, v1, v2, e0, e1, e2, even0);
            }
        }
    } else {
        float fxf = floorf(px), fyf = floorf(py), fzf = floorf(pz);
        int ix0 = (int)fxf, iy0 = (int)fyf, iz0 = (int)fzf;  // iz0 in [0,6]
        float fx = px - fxf, fy = py - fyf, fz = pz - fzf;

        float ox[2] = { fminf(1.0f - fx, sx), fmaxf(fx + sx - 1.0f, 0.0f) };
        float oy[2] = { fminf(1.0f - fy, sy), fmaxf(fy + sy - 1.0f, 0.0f) };
        float v0 = fminf(1.0f - fz, sz);
        float v1 = fmaxf(fz + sz - 1.0f, 0.0f);
        bool e0 = (iz0 >= 1);
        bool e1 = (iz0 <= 5) & (v1 > 0.0f);
        bool even0 = ((iz0 & 1) == 0);

        cudaGridDependencySynchronize();       // wait for zeroed grid
        if (!(e0 | e1)) return;

#pragma unroll
        for (int b = 0; b < 2; ++b) {
            if (oy[b] == 0.0f) continue;
#pragma unroll
            for (int a = 0; a < 2; ++a) {
                if (ox[a] == 0.0f) continue;
                float wxy = ox[a] * oy[b];
                float* p = GRID_B + (((ix0 + a) * NY_ + (iy0 + b)) << 3) + iz0;
                if (e0 && e1 && even0) red2(p, wxy * v0, wxy * v1);
                else {
                    if (e0) red1(p, wxy * v0);
                    if (e1) red1(p + 1, wxy * v1);
                }
            }
        }
    }
    cudaTriggerProgrammaticLaunchCompletion();
}

// ---------------------------------------------------------------------------
// Reduction (load-only, champion config): one thread per (x,y) z-row,
// 2x float4, interior z=1..6. PDL: index math pre-sync; loads post-sync.
// ---------------------------------------------------------------------------
__global__ void k_reduce(float* __restrict__ out) {
    int t = blockIdx.x * blockDim.x + threadIdx.x;  // 512*512 threads
    float s = 0.0f, m = 0.0f;
    int ix = t >> 9;
    int iy = t & 511;
    bool interior = (ix >= 1) & (ix <= NX_ - 2) & (iy >= 1) & (iy <= NY_ - 2);

    cudaGridDependencySynchronize();           // wait for scatter's REDs

    if (interior) {
        const float4* g4 = reinterpret_cast<const float4*>(GRID_B) + t * 2;
        float4 a = g4[0];
        float4 b = g4[1];
        s = fmaxf(a.y - 1.0f, 0.0f) + fmaxf(a.z - 1.0f, 0.0f) +
            fmaxf(a.w - 1.0f, 0.0f) + fmaxf(b.x - 1.0f, 0.0f) +
            fmaxf(b.y - 1.0f, 0.0f) + fmaxf(b.z - 1.0f, 0.0f);
        m = fmaxf(fmaxf(fmaxf(a.y, a.z), fmaxf(a.w, b.x)), fmaxf(b.y, b.z));
    }
#pragma unroll
    for (int o = 16; o > 0; o >>= 1) {
        s += __shfl_down_sync(0xffffffffu, s, o);
        m = fmaxf(m, __shfl_down_sync(0xffffffffu, m, o));
    }
    __shared__ float ss[8], sm[8];
    int lane = threadIdx.x & 31;
    int wid = threadIdx.x >> 5;
    if (lane == 0) { ss[wid] = s; sm[wid] = m; }
    __syncthreads();
    if (wid == 0) {
        int nw = blockDim.x >> 5;
        s = (lane < nw) ? ss[lane] : 0.0f;
        m = (lane < nw) ? sm[lane] : 0.0f;
#pragma unroll
        for (int o = 4; o > 0; o >>= 1) {
            s += __shfl_down_sync(0xffffffffu, s, o);
            m = fmaxf(m, __shfl_down_sync(0xffffffffu, m, o));
        }
        if (lane == 0) {
            atomicAdd(&out[0], s);
            atomicMax(reinterpret_cast<int*>(&out[1]), __float_as_int(m));
        }
    }
}

extern "C" void kernel_launch(void* const* d_in, const int* in_sizes, int n_in,
                              void* d_out, int out_size) {
    const float* pos = (const float*)d_in[0];
    const float* nsx = (const float*)d_in[1];
    const float* nsy = (const float*)d_in[2];
    const float* nsz = (const float*)d_in[3];
    float* out = (float*)d_out;

    // 1) zero (plain launch)
    k_zero<<<512, 256>>>(out);

    // 2) scatter — PDL-dependent on zero
    {
        cudaLaunchConfig_t cfg = {};
        cfg.gridDim = dim3((N_ + 255) / 256);
        cfg.blockDim = dim3(256);
        cudaLaunchAttribute attr[1];
        attr[0].id = cudaLaunchAttributeProgrammaticStreamSerialization;
        attr[0].val.programmaticStreamSerializationAllowed = 1;
        cfg.attrs = attr;
        cfg.numAttrs = 1;
        cudaLaunchKernelEx(&cfg, k_scatter, pos, nsx, nsy, nsz);
    }

    // 3) reduce — PDL-dependent on scatter
    {
        cudaLaunchConfig_t cfg = {};
        cfg.gridDim = dim3((NX_ * NY_) / 256);
        cfg.blockDim = dim3(256);
        cudaLaunchAttribute attr[1];
        attr[0].id = cudaLaunchAttributeProgrammaticStreamSerialization;
        attr[0].val.programmaticStreamSerializationAllowed = 1;
        cfg.attrs = attr;
        cfg.numAttrs = 1;
        cudaLaunchKernelEx(&cfg, k_reduce, out);
    }
}